// round 4
// baseline (speedup 1.0000x reference)
#include <cuda_runtime.h>
#include <math.h>

#define BB   8192
#define DD   512
#define HH   8
#define MM   16
#define HDD  64
#define D4X  (4*DD)

// ---------------- scratch (device globals; no allocation allowed) ----------------
__device__ float g_xin [BB*DD];
__device__ float g_y1  [BB*DD];
__device__ float g_q   [BB*DD];
__device__ float g_k   [BB*MM*DD];
__device__ float g_v   [BB*MM*DD];
__device__ float g_ctx [BB*DD];
__device__ float g_xmid[BB*DD];
__device__ float g_y2  [BB*DD];
__device__ float g_h   [BB*D4X];

__device__ __forceinline__ float sigmoidf_(float x) { return 1.f / (1.f + expf(-x)); }

// ---------------- kernel 1: gated input + write mem slot 15 ----------------
__global__ void k_xin(const float* __restrict__ x, const float* __restrict__ ssum,
                      const float* __restrict__ alpha, float* __restrict__ out_mem,
                      float* __restrict__ xin)
{
    int i = blockIdx.x * blockDim.x + threadIdx.x;            // over BB*DD/4
    if (i >= BB * DD / 4) return;
    int d4 = i & (DD/4 - 1);
    int b  = i >> 7;                                           // i / (DD/4)
    float4 xv = ((const float4*)x)[i];
    float4 sv = ((const float4*)ssum)[i];
    float4 av = ((const float4*)alpha)[d4];
    float4 r;
    r.x = xv.x + sv.x * sigmoidf_(av.x);
    r.y = xv.y + sv.y * sigmoidf_(av.y);
    r.z = xv.z + sv.z * sigmoidf_(av.z);
    r.w = xv.w + sv.w * sigmoidf_(av.w);
    ((float4*)xin)[i] = r;
    ((float4*)out_mem)[(size_t)(b*MM + (MM-1)) * (DD/4) + d4] = r;
}

// ---------------- kernel 2: sliding-window copy mem[:,1:,:] -> out_mem[:,0:15,:] ----------------
__global__ void k_copy(const float* __restrict__ mem, float* __restrict__ out_mem)
{
    int i = blockIdx.x * blockDim.x + threadIdx.x;            // over BB*15*DD/4
    const int n = BB * (MM-1) * DD / 4;
    if (i >= n) return;
    const int per_b = (MM-1) * (DD/4);
    int b  = i / per_b;
    int r  = i - b * per_b;
    int t  = r >> 7;                                           // r / (DD/4)
    int d4 = r & (DD/4 - 1);
    ((float4*)out_mem)[(size_t)(b*MM + t) * (DD/4) + d4] =
        ((const float4*)mem)[(size_t)(b*MM + t + 1) * (DD/4) + d4];
}

// ---------------- LayerNorm: one warp per row of 512 ----------------
__global__ void k_ln(const float* __restrict__ in, const float* __restrict__ scale,
                     const float* __restrict__ bias, float* __restrict__ out)
{
    int gw   = (blockIdx.x * blockDim.x + threadIdx.x) >> 5;
    int lane = threadIdx.x & 31;
    if (gw >= BB) return;
    const float4* row = (const float4*)(in + (size_t)gw * DD);
    float4 v[4];
    float s = 0.f;
#pragma unroll
    for (int j = 0; j < 4; j++) {
        v[j] = row[lane + 32*j];
        s += v[j].x + v[j].y + v[j].z + v[j].w;
    }
#pragma unroll
    for (int o = 16; o; o >>= 1) s += __shfl_xor_sync(0xffffffffu, s, o);
    float mu = s * (1.f / DD);
    float var = 0.f;
#pragma unroll
    for (int j = 0; j < 4; j++) {
        float a = v[j].x - mu, b = v[j].y - mu, c = v[j].z - mu, d = v[j].w - mu;
        var += a*a + b*b + c*c + d*d;
    }
#pragma unroll
    for (int o = 16; o; o >>= 1) var += __shfl_xor_sync(0xffffffffu, var, o);
    float inv = rsqrtf(var * (1.f / DD) + 1e-6f);
    float4* orow = (float4*)(out + (size_t)gw * DD);
    const float4* sc = (const float4*)scale;
    const float4* bi = (const float4*)bias;
#pragma unroll
    for (int j = 0; j < 4; j++) {
        float4 sv = sc[lane + 32*j];
        float4 bv = bi[lane + 32*j];
        float4 o4;
        o4.x = (v[j].x - mu) * inv * sv.x + bv.x;
        o4.y = (v[j].y - mu) * inv * sv.y + bv.y;
        o4.z = (v[j].z - mu) * inv * sv.z + bv.z;
        o4.w = (v[j].w - mu) * inv * sv.w + bv.w;
        orow[lane + 32*j] = o4;
    }
}

// ---------------- SGEMM: 128x128 block tile, 8x8 per thread, K-tile 8, double-buffered ----------------
// EPI: 0 = +bias; 1 = +bias +res; 2 = +bias then gelu(tanh); 3 = +bias +res, write C and gated ssum
template<int EPI>
__global__ void __launch_bounds__(256) sgemm_k(
    const float* __restrict__ A, const float* __restrict__ W,
    const float* __restrict__ bias, const float* __restrict__ res,
    float* __restrict__ C, int M, int N, int K,
    const float* __restrict__ ss_in, const float* __restrict__ lam,
    float* __restrict__ ss_out)
{
    __shared__ float As[2][8][128];
    __shared__ float Bs[2][8][128];

    const int tid  = threadIdx.x;
    const int tx   = tid & 15;
    const int ty   = tid >> 4;
    const int aRow = tid >> 1;
    const int aCol = (tid & 1) << 2;
    const int bRow = tid >> 5;
    const int bCol = (tid & 31) << 2;

    const float* Ap = A + (size_t)(blockIdx.y * 128 + aRow) * K + aCol;
    const float* Bp = W + (size_t)bRow * N + blockIdx.x * 128 + bCol;

    float4 aR = *(const float4*)Ap;
    float4 bR = *(const float4*)Bp;
    As[0][aCol+0][aRow] = aR.x; As[0][aCol+1][aRow] = aR.y;
    As[0][aCol+2][aRow] = aR.z; As[0][aCol+3][aRow] = aR.w;
    *(float4*)&Bs[0][bRow][bCol] = bR;
    __syncthreads();

    float acc[8][8];
#pragma unroll
    for (int i = 0; i < 8; i++)
#pragma unroll
        for (int j = 0; j < 8; j++) acc[i][j] = 0.f;

    const int nk = K >> 3;
    for (int kk = 0; kk < nk; kk++) {
        const int cur = kk & 1;
        if (kk + 1 < nk) {
            aR = *(const float4*)(Ap + (kk+1)*8);
            bR = *(const float4*)(Bp + (size_t)(kk+1)*8*N);
        }
#pragma unroll
        for (int k = 0; k < 8; k++) {
            float av[8], bv[8];
            *(float4*)&av[0] = *(const float4*)&As[cur][k][ty*8];
            *(float4*)&av[4] = *(const float4*)&As[cur][k][ty*8+4];
            *(float4*)&bv[0] = *(const float4*)&Bs[cur][k][tx*8];
            *(float4*)&bv[4] = *(const float4*)&Bs[cur][k][tx*8+4];
#pragma unroll
            for (int i = 0; i < 8; i++)
#pragma unroll
                for (int j = 0; j < 8; j++)
                    acc[i][j] = fmaf(av[i], bv[j], acc[i][j]);
        }
        if (kk + 1 < nk) {
            const int nxt = cur ^ 1;
            As[nxt][aCol+0][aRow] = aR.x; As[nxt][aCol+1][aRow] = aR.y;
            As[nxt][aCol+2][aRow] = aR.z; As[nxt][aCol+3][aRow] = aR.w;
            *(float4*)&Bs[nxt][bRow][bCol] = bR;
        }
        __syncthreads();
    }

    const int row0 = blockIdx.y * 128 + ty * 8;
    const int col0 = blockIdx.x * 128 + tx * 8;
    float bb[8], sg[8];
#pragma unroll
    for (int j = 0; j < 8; j++) bb[j] = bias[col0 + j];
    if (EPI == 3) {
#pragma unroll
        for (int j = 0; j < 8; j++) sg[j] = 1.f / (1.f + expf(-lam[col0 + j]));
    }
#pragma unroll
    for (int i = 0; i < 8; i++) {
        const size_t off = (size_t)(row0 + i) * N + col0;
        float out[8];
#pragma unroll
        for (int j = 0; j < 8; j++) {
            float vv = acc[i][j] + bb[j];
            if (EPI == 1 || EPI == 3) vv += res[off + j];
            if (EPI == 2) {
                float u = vv;
                float t = tanhf(0.7978845608028654f * (u + 0.044715f * u * u * u));
                vv = 0.5f * u * (1.f + t);
            }
            out[j] = vv;
        }
        *(float4*)&C[off]     = *(float4*)&out[0];
        *(float4*)&C[off + 4] = *(float4*)&out[4];
        if (EPI == 3) {
            float so[8];
#pragma unroll
            for (int j = 0; j < 8; j++)
                so[j] = ss_in[off + j] * sg[j] + out[j] * (1.f - sg[j]);
            *(float4*)&ss_out[off]     = *(float4*)&so[0];
            *(float4*)&ss_out[off + 4] = *(float4*)&so[4];
        }
    }
}

// ---------------- attention: one warp per (b, h); q-len 1, kv-len 16 ----------------
__global__ void k_attn(const float* __restrict__ q, const float* __restrict__ k,
                       const float* __restrict__ v, float* __restrict__ ctx)
{
    int gw   = (blockIdx.x * blockDim.x + threadIdx.x) >> 5;
    int lane = threadIdx.x & 31;
    if (gw >= BB * HH) return;
    int b = gw >> 3;
    int h = gw & 7;

    const float* qp = q + (size_t)b * DD + h * HDD;
    float q0 = qp[lane], q1 = qp[lane + 32];

    float s[MM];
    const float* kb = k + (size_t)b * MM * DD + h * HDD;
#pragma unroll
    for (int t = 0; t < MM; t++) {
        const float* kp = kb + t * DD;
        float p = q0 * kp[lane] + q1 * kp[lane + 32];
#pragma unroll
        for (int o = 16; o; o >>= 1) p += __shfl_xor_sync(0xffffffffu, p, o);
        s[t] = p * 0.125f;   // 1/sqrt(64)
    }
    float mx = s[0];
#pragma unroll
    for (int t = 1; t < MM; t++) mx = fmaxf(mx, s[t]);
    float sum = 0.f;
#pragma unroll
    for (int t = 0; t < MM; t++) { s[t] = expf(s[t] - mx); sum += s[t]; }
    float inv = 1.f / sum;

    float c0 = 0.f, c1 = 0.f;
    const float* vb = v + (size_t)b * MM * DD + h * HDD;
#pragma unroll
    for (int t = 0; t < MM; t++) {
        float w = s[t] * inv;
        c0 = fmaf(w, vb[t * DD + lane],      c0);
        c1 = fmaf(w, vb[t * DD + lane + 32], c1);
    }
    ctx[(size_t)b * DD + h * HDD + lane]      = c0;
    ctx[(size_t)b * DD + h * HDD + lane + 32] = c1;
}

// ---------------- launch ----------------
extern "C" void kernel_launch(void* const* d_in, const int* in_sizes, int n_in,
                              void* d_out, int out_size)
{
    const float* mem   = (const float*)d_in[0];
    const float* ssum  = (const float*)d_in[1];
    const float* x     = (const float*)d_in[2];
    const float* alpha = (const float*)d_in[3];
    const float* lam   = (const float*)d_in[4];
    const float* ln1s  = (const float*)d_in[5];
    const float* ln1b  = (const float*)d_in[6];
    const float* ln2s  = (const float*)d_in[7];
    const float* ln2b  = (const float*)d_in[8];
    const float* wq    = (const float*)d_in[9];
    const float* bq    = (const float*)d_in[10];
    const float* wk    = (const float*)d_in[11];
    const float* bk    = (const float*)d_in[12];
    const float* wv    = (const float*)d_in[13];
    const float* bv    = (const float*)d_in[14];
    const float* wo    = (const float*)d_in[15];
    const float* bo    = (const float*)d_in[16];
    const float* w1    = (const float*)d_in[17];
    const float* b1    = (const float*)d_in[18];
    const float* w2    = (const float*)d_in[19];
    const float* b2    = (const float*)d_in[20];

    float* out_mem  = (float*)d_out;                       // [B, MEM, D]
    float* out_ssum = out_mem + (size_t)BB * MM * DD;      // [B, D]
    float* out_x    = out_ssum + (size_t)BB * DD;          // [B, D]

    float *p_xin, *p_y1, *p_q, *p_k, *p_v, *p_ctx, *p_xmid, *p_y2, *p_h;
    cudaGetSymbolAddress((void**)&p_xin,  g_xin);
    cudaGetSymbolAddress((void**)&p_y1,   g_y1);
    cudaGetSymbolAddress((void**)&p_q,    g_q);
    cudaGetSymbolAddress((void**)&p_k,    g_k);
    cudaGetSymbolAddress((void**)&p_v,    g_v);
    cudaGetSymbolAddress((void**)&p_ctx,  g_ctx);
    cudaGetSymbolAddress((void**)&p_xmid, g_xmid);
    cudaGetSymbolAddress((void**)&p_y2,   g_y2);
    cudaGetSymbolAddress((void**)&p_h,    g_h);

    // 1) gated input + memory slot 15
    k_xin<<<(BB*DD/4 + 255) / 256, 256>>>(x, ssum, alpha, out_mem, p_xin);
    // 2) shift old memory
    k_copy<<<(BB*(MM-1)*DD/4 + 255) / 256, 256>>>(mem, out_mem);
    // 3) LN1
    k_ln<<<BB/8, 256>>>(p_xin, ln1s, ln1b, p_y1);
    // 4) q = LN1(x_in) @ wq + bq
    sgemm_k<0><<<dim3(DD/128, BB/128), 256>>>(p_y1, wq, bq, nullptr, p_q,
                                              BB, DD, DD, nullptr, nullptr, nullptr);
    // 5) k = updated_mem @ wk + bk
    sgemm_k<0><<<dim3(DD/128, BB*MM/128), 256>>>(out_mem, wk, bk, nullptr, p_k,
                                                 BB*MM, DD, DD, nullptr, nullptr, nullptr);
    // 6) v = updated_mem @ wv + bv
    sgemm_k<0><<<dim3(DD/128, BB*MM/128), 256>>>(out_mem, wv, bv, nullptr, p_v,
                                                 BB*MM, DD, DD, nullptr, nullptr, nullptr);
    // 7) attention
    k_attn<<<BB*HH/8, 256>>>(p_q, p_k, p_v, p_ctx);
    // 8) x_mid = x_in + ctx @ wo + bo
    sgemm_k<1><<<dim3(DD/128, BB/128), 256>>>(p_ctx, wo, bo, p_xin, p_xmid,
                                              BB, DD, DD, nullptr, nullptr, nullptr);
    // 9) LN2
    k_ln<<<BB/8, 256>>>(p_xmid, ln2s, ln2b, p_y2);
    // 10) h = gelu(y2 @ w1 + b1)
    sgemm_k<2><<<dim3(D4X/128, BB/128), 256>>>(p_y2, w1, b1, nullptr, p_h,
                                               BB, D4X, DD, nullptr, nullptr, nullptr);
    // 11) x_out = x_mid + h @ w2 + b2 ; new_ssum = ssum*sig(lam) + x_out*(1-sig(lam))
    sgemm_k<3><<<dim3(DD/128, BB/128), 256>>>(p_h, w2, b2, p_xmid, out_x,
                                              BB, DD, D4X, ssum, lam, out_ssum);
}